// round 1
// baseline (speedup 1.0000x reference)
#include <cuda_runtime.h>
#include <math.h>

#define BB    2
#define CC    256
#define HFD   60
#define WFD   60
#define NPix  3600          // HFD*WFD
#define NCls  2
#define HOUT  473
#define WOUT  473
#define NCHUNK 8

// ---------------- scratch (device globals; no allocation allowed) ----------------
__device__ float g_Wv[BB*CC*NPix];          // W_e @ V_a            [b][d][n]
__device__ float g_S [BB*NPix*NPix];        // affinity             [b][n][m]
__device__ float g_P [BB*NPix*NPix];        // softmax probs (reused col then row)
__device__ float g_rowmax[BB*NPix];
__device__ float g_rowinv[BB*NPix];
__device__ float g_cpm[NCHUNK*BB*NPix];     // col-stat partial max
__device__ float g_cps[NCHUNK*BB*NPix];     // col-stat partial sum
__device__ float g_colmax[BB*NPix];
__device__ float g_colinv[BB*NPix];
__device__ float g_att1[BB*CC*NPix];        // Z_a (gated in place)
__device__ float g_att2[BB*CC*NPix];        // Z_b (gated in place)
__device__ float g_x1[BB*CC*NPix];          // conv1 out (pre-BN)
__device__ float g_x2[BB*CC*NPix];          // conv2 out (pre-BN)
__device__ float g_bnsc1[CC], g_bnsh1[CC];
__device__ float g_bnsc2[CC], g_bnsh2[CC];
__device__ float g_y1[BB*NCls*NPix];        // logits branch 1 (60x60)
__device__ float g_y2[BB*NCls*NPix];        // logits branch 2 (60x60)

// ---------------- generic tiled fp32 GEMM: C[M,N] = A*B ----------------
// AMODE 0: A element (i,k) at A[i*Kd+k]   (row-major M x K)
// AMODE 1: A element (i,k) at A[k*Md+i]   (K x M, "transposed")
// BMODE 0: B element (k,j) at B[k*Nd+j]
// BMODE 1: B element (k,j) at B[j*Kd+k]
// Tile 128x64, BK=16, 256 threads, 8x4 per thread. Requires Kd%16==0, Nd%4==0, Md%8==0.
template<int AMODE, int BMODE>
__global__ void __launch_bounds__(256)
gemm_tiled(const float* __restrict__ A, const float* __restrict__ Bp,
           float* __restrict__ Cc, int Md, int Nd, int Kd,
           size_t sA, size_t sB, size_t sC)
{
    A  += (size_t)blockIdx.z * sA;
    Bp += (size_t)blockIdx.z * sB;
    Cc += (size_t)blockIdx.z * sC;

    __shared__ float As[16][128];
    __shared__ float Bs[16][64];

    const int m0 = blockIdx.y * 128;
    const int n0 = blockIdx.x * 64;
    const int tid = threadIdx.x;
    const int tx = tid & 15;      // column group
    const int ty = tid >> 4;      // row group

    float acc[8][4];
#pragma unroll
    for (int r = 0; r < 8; r++)
#pragma unroll
        for (int c = 0; c < 4; c++) acc[r][c] = 0.f;

    for (int k0 = 0; k0 < Kd; k0 += 16) {
        // ---- load A tile (16 x 128, K-major in smem) ----
        if (AMODE == 0) {
            int il  = tid >> 1;
            int i   = m0 + il;
            int kof = (tid & 1) * 8;
            float4 v0 = make_float4(0,0,0,0), v1 = v0;
            if (i < Md) {
                const float* ap = A + (size_t)i * Kd + k0 + kof;
                v0 = *(const float4*)ap;
                v1 = *(const float4*)(ap + 4);
            }
            As[kof+0][il]=v0.x; As[kof+1][il]=v0.y; As[kof+2][il]=v0.z; As[kof+3][il]=v0.w;
            As[kof+4][il]=v1.x; As[kof+5][il]=v1.y; As[kof+6][il]=v1.z; As[kof+7][il]=v1.w;
        } else {
            int k   = tid >> 4;
            int iof = (tid & 15) * 8;
            int i   = m0 + iof;
            float4 v0 = make_float4(0,0,0,0), v1 = v0;
            if (i < Md) {
                const float* ap = A + (size_t)(k0 + k) * Md + i;
                v0 = *(const float4*)ap;
                v1 = *(const float4*)(ap + 4);
            }
            *(float4*)&As[k][iof]     = v0;
            *(float4*)&As[k][iof + 4] = v1;
        }
        // ---- load B tile (16 x 64) ----
        if (BMODE == 0) {
            int k   = tid >> 4;
            int jof = (tid & 15) * 4;
            int j   = n0 + jof;
            float4 v = make_float4(0,0,0,0);
            if (j < Nd) v = *(const float4*)(Bp + (size_t)(k0 + k) * Nd + j);
            *(float4*)&Bs[k][jof] = v;
        } else {
            int jof = tid >> 2;
            int j   = n0 + jof;
            int kof = (tid & 3) * 4;
            float4 v = make_float4(0,0,0,0);
            if (j < Nd) v = *(const float4*)(Bp + (size_t)j * Kd + k0 + kof);
            Bs[kof+0][jof]=v.x; Bs[kof+1][jof]=v.y; Bs[kof+2][jof]=v.z; Bs[kof+3][jof]=v.w;
        }
        __syncthreads();

#pragma unroll
        for (int k = 0; k < 16; k++) {
            float4 a0 = *(const float4*)&As[k][ty*8];
            float4 a1 = *(const float4*)&As[k][ty*8+4];
            float4 b  = *(const float4*)&Bs[k][tx*4];
            float av[8] = {a0.x,a0.y,a0.z,a0.w,a1.x,a1.y,a1.z,a1.w};
            float bv[4] = {b.x,b.y,b.z,b.w};
#pragma unroll
            for (int r = 0; r < 8; r++)
#pragma unroll
                for (int c = 0; c < 4; c++)
                    acc[r][c] += av[r] * bv[c];
        }
        __syncthreads();
    }

    int j = n0 + tx*4;
    if (j < Nd) {
#pragma unroll
        for (int r = 0; r < 8; r++) {
            int i = m0 + ty*8 + r;
            if (i < Md)
                *(float4*)&Cc[(size_t)i * Nd + j] =
                    make_float4(acc[r][0], acc[r][1], acc[r][2], acc[r][3]);
        }
    }
}

// ---------------- 3x3 conv as implicit GEMM (pad=1), channel-concat input ----------------
__global__ void __launch_bounds__(256)
conv3x3_gemm(const float* __restrict__ Wt, const float* __restrict__ s0,
             const float* __restrict__ s1, const float* __restrict__ s2,
             float* __restrict__ out, int CinTot)
{
    const int b  = blockIdx.z;
    const int Kd = CinTot * 9;

    __shared__ float As[16][128];
    __shared__ float Bs[16][64];

    const int m0 = blockIdx.y * 128;
    const int n0 = blockIdx.x * 64;
    const int tid = threadIdx.x;
    const int tx = tid & 15, ty = tid >> 4;

    float acc[8][4];
#pragma unroll
    for (int r = 0; r < 8; r++)
#pragma unroll
        for (int c = 0; c < 4; c++) acc[r][c] = 0.f;

    for (int k0 = 0; k0 < Kd; k0 += 16) {
        // A: weights [256][Kd]
        {
            int il  = tid >> 1;
            int i   = m0 + il;
            int kof = (tid & 1) * 8;
            const float* ap = Wt + (size_t)i * Kd + k0 + kof;
            float4 v0 = *(const float4*)ap;
            float4 v1 = *(const float4*)(ap + 4);
            As[kof+0][il]=v0.x; As[kof+1][il]=v0.y; As[kof+2][il]=v0.z; As[kof+3][il]=v0.w;
            As[kof+4][il]=v1.x; As[kof+5][il]=v1.y; As[kof+6][il]=v1.z; As[kof+7][il]=v1.w;
        }
        // B: im2col gather from concatenated sources
        {
            int k   = tid >> 4;
            int jof = (tid & 15) * 4;
            int kk  = k0 + k;
            int ci  = kk / 9;
            int rr  = kk - ci * 9;
            int kh  = rr / 3;
            int kw  = rr - kh * 3;
            const float* sp = (ci < 256) ? s0 : ((ci < 512) ? s1 : s2);
            int cl = ci & 255;
            const float* base = sp + (size_t)(b * CC + cl) * NPix;
#pragma unroll
            for (int u = 0; u < 4; u++) {
                int j = n0 + jof + u;
                float v = 0.f;
                if (j < NPix) {
                    int h = j / 60, w = j - h * 60;
                    int ih = h + kh - 1, iw = w + kw - 1;
                    if ((unsigned)ih < 60u && (unsigned)iw < 60u)
                        v = base[ih * 60 + iw];
                }
                Bs[k][jof + u] = v;
            }
        }
        __syncthreads();

#pragma unroll
        for (int k = 0; k < 16; k++) {
            float4 a0 = *(const float4*)&As[k][ty*8];
            float4 a1 = *(const float4*)&As[k][ty*8+4];
            float4 bq = *(const float4*)&Bs[k][tx*4];
            float av[8] = {a0.x,a0.y,a0.z,a0.w,a1.x,a1.y,a1.z,a1.w};
            float bv[4] = {bq.x,bq.y,bq.z,bq.w};
#pragma unroll
            for (int r = 0; r < 8; r++)
#pragma unroll
                for (int c = 0; c < 4; c++)
                    acc[r][c] += av[r] * bv[c];
        }
        __syncthreads();
    }

    int j = n0 + tx*4;
    if (j < NPix) {
#pragma unroll
        for (int r = 0; r < 8; r++) {
            int i = m0 + ty*8 + r;   // co
            *(float4*)&out[(size_t)(b * CC + i) * NPix + j] =
                make_float4(acc[r][0], acc[r][1], acc[r][2], acc[r][3]);
        }
    }
}

// ---------------- softmax statistics ----------------
__global__ void rowstats_kernel()
{
    int row = blockIdx.x;                    // b*NPix + n
    const float* Sr = g_S + (size_t)row * NPix;
    float m = -1e30f, s = 0.f;
    for (int j = threadIdx.x; j < NPix; j += 256) {
        float v = Sr[j];
        if (v > m) { s *= __expf(m - v); m = v; }
        s += __expf(v - m);
    }
    __shared__ float sm[256], ss[256];
    sm[threadIdx.x] = m; ss[threadIdx.x] = s;
    __syncthreads();
    for (int off = 128; off; off >>= 1) {
        if (threadIdx.x < off) {
            float m1 = sm[threadIdx.x], s1 = ss[threadIdx.x];
            float m2 = sm[threadIdx.x + off], s2 = ss[threadIdx.x + off];
            float M = fmaxf(m1, m2);
            sm[threadIdx.x] = M;
            ss[threadIdx.x] = s1 * __expf(m1 - M) + s2 * __expf(m2 - M);
        }
        __syncthreads();
    }
    if (threadIdx.x == 0) { g_rowmax[row] = sm[0]; g_rowinv[row] = 1.f / ss[0]; }
}

__global__ void colstats_part()
{
    int mcol = blockIdx.x * 256 + threadIdx.x;
    int ch = blockIdx.y, b = blockIdx.z;
    if (mcol >= NPix) return;
    const int rows = NPix / NCHUNK;          // 450
    const float* Sp = g_S + (size_t)b * NPix * NPix + (size_t)(ch * rows) * NPix + mcol;
    float m = -1e30f, s = 0.f;
    for (int n = 0; n < rows; n++) {
        float v = Sp[(size_t)n * NPix];
        if (v > m) { s *= __expf(m - v); m = v; }
        s += __expf(v - m);
    }
    g_cpm[(size_t)(ch * BB + b) * NPix + mcol] = m;
    g_cps[(size_t)(ch * BB + b) * NPix + mcol] = s;
}

__global__ void colstats_comb()
{
    int mcol = blockIdx.x * 256 + threadIdx.x;
    int b = blockIdx.z;
    if (mcol >= NPix) return;
    float M = -1e30f, S = 0.f;
    for (int ch = 0; ch < NCHUNK; ch++) {
        float m2 = g_cpm[(size_t)(ch * BB + b) * NPix + mcol];
        float s2 = g_cps[(size_t)(ch * BB + b) * NPix + mcol];
        float Mn = fmaxf(M, m2);
        S = S * __expf(M - Mn) + s2 * __expf(m2 - Mn);
        M = Mn;
    }
    g_colmax[b * NPix + mcol] = M;
    g_colinv[b * NPix + mcol] = 1.f / S;
}

// P[n,m] = exp(S[n,m]-colmax[m]) / colsum[m]
__global__ void expcol_kernel()
{
    int row = blockIdx.x;                    // b*NPix + n
    int b = row / NPix;
    const float* Sr = g_S + (size_t)row * NPix;
    float* Pr = g_P + (size_t)row * NPix;
    const float* cm = g_colmax + (size_t)b * NPix;
    const float* ci = g_colinv + (size_t)b * NPix;
    for (int j = threadIdx.x; j < NPix; j += 256)
        Pr[j] = __expf(Sr[j] - cm[j]) * ci[j];
}

// P[n,m] = exp(S[n,m]-rowmax[n]) / rowsum[n]
__global__ void exprow_kernel()
{
    int row = blockIdx.x;
    const float* Sr = g_S + (size_t)row * NPix;
    float* Pr = g_P + (size_t)row * NPix;
    float rm = g_rowmax[row], ri = g_rowinv[row];
    for (int j = threadIdx.x; j < NPix; j += 256)
        Pr[j] = __expf(Sr[j] - rm) * ri;
}

// ---------------- gate: Z *= sigmoid(sum_c gate_w[c]*Z[c]) ----------------
__global__ void gate_kernel(float* __restrict__ Z, const float* __restrict__ gw)
{
    int b = blockIdx.z;
    int pix = blockIdx.x * 256 + threadIdx.x;
    __shared__ float w[CC];
    for (int c = threadIdx.x; c < CC; c += 256) w[c] = gw[c];
    __syncthreads();
    if (pix >= NPix) return;
    float* zp = Z + (size_t)b * CC * NPix + pix;
    float g = 0.f;
    for (int c = 0; c < CC; c++) g += w[c] * zp[(size_t)c * NPix];
    float sg = 1.f / (1.f + __expf(-g));
    for (int c = 0; c < CC; c++) zp[(size_t)c * NPix] *= sg;
}

// ---------------- BN batch stats -> scale/shift ----------------
__global__ void bnstats_kernel(const float* __restrict__ x,
                               const float* __restrict__ gam,
                               const float* __restrict__ bet,
                               float* __restrict__ scale, float* __restrict__ shift)
{
    int c = blockIdx.x;
    float s = 0.f, q = 0.f;
    for (int b = 0; b < BB; b++) {
        const float* xp = x + (size_t)(b * CC + c) * NPix;
        for (int i = threadIdx.x; i < NPix; i += 256) {
            float v = xp[i];
            s += v; q += v * v;
        }
    }
    __shared__ float rs[256], rq[256];
    rs[threadIdx.x] = s; rq[threadIdx.x] = q;
    __syncthreads();
    for (int off = 128; off; off >>= 1) {
        if (threadIdx.x < off) {
            rs[threadIdx.x] += rs[threadIdx.x + off];
            rq[threadIdx.x] += rq[threadIdx.x + off];
        }
        __syncthreads();
    }
    if (threadIdx.x == 0) {
        const float inv = 1.f / (BB * NPix);
        float mean = rs[0] * inv;
        float var  = rq[0] * inv - mean * mean;
        float sc = gam[c] * rsqrtf(var + 1e-5f);
        scale[c] = sc;
        shift[c] = bet[c] - mean * sc;
    }
}

// ---------------- fused BN + ReLU + 1x1 classifier ----------------
__global__ void bncls_kernel(const float* __restrict__ x,
                             const float* __restrict__ scale, const float* __restrict__ shift,
                             const float* __restrict__ cw, const float* __restrict__ cb,
                             float* __restrict__ y)
{
    int b = blockIdx.z;
    int pix = blockIdx.x * 256 + threadIdx.x;
    __shared__ float sc[CC], sh[CC], w0[CC], w1[CC];
    for (int c = threadIdx.x; c < CC; c += 256) {
        sc[c] = scale[c]; sh[c] = shift[c];
        w0[c] = cw[c];    w1[c] = cw[CC + c];
    }
    __syncthreads();
    if (pix >= NPix) return;
    const float* xp = x + (size_t)b * CC * NPix + pix;
    float a0 = cb[0], a1 = cb[1];
    for (int c = 0; c < CC; c++) {
        float v = xp[(size_t)c * NPix] * sc[c] + sh[c];
        v = fmaxf(v, 0.f);
        a0 += v * w0[c];
        a1 += v * w1[c];
    }
    y[(size_t)(b * NCls + 0) * NPix + pix] = a0;
    y[(size_t)(b * NCls + 1) * NPix + pix] = a1;
}

// ---------------- bilinear resize 60->473 (half-pixel centers) + sigmoid ----------------
__global__ void resize_kernel(float* __restrict__ out)
{
    const size_t per = (size_t)BB * NCls * HOUT * WOUT;
    size_t idx = (size_t)blockIdx.x * 256 + threadIdx.x;
    if (idx >= 2 * per) return;
    int t = idx >= per;
    size_t r = idx - (size_t)t * per;
    int x = (int)(r % WOUT); r /= WOUT;
    int y = (int)(r % HOUT); r /= HOUT;
    int kc = (int)(r % NCls);
    int b  = (int)(r / NCls);
    const float* src = (t ? g_y2 : g_y1) + (size_t)(b * NCls + kc) * NPix;

    const float sc = 60.f / 473.f;
    float syf = (y + 0.5f) * sc - 0.5f;
    float sxf = (x + 0.5f) * sc - 0.5f;
    float fy0 = floorf(syf), fx0 = floorf(sxf);
    float fy = syf - fy0,    fx = sxf - fx0;
    int y0 = (int)fy0, x0 = (int)fx0;
    int y1i = min(y0 + 1, 59), x1i = min(x0 + 1, 59);
    y0 = max(y0, 0); x0 = max(x0, 0);

    float v00 = src[y0  * 60 + x0 ];
    float v01 = src[y0  * 60 + x1i];
    float v10 = src[y1i * 60 + x0 ];
    float v11 = src[y1i * 60 + x1i];
    float vt = v00 + (v01 - v00) * fx;
    float vb = v10 + (v11 - v10) * fx;
    float v  = vt + (vb - vt) * fy;

    out[idx] = 1.f / (1.f + __expf(-v));
}

// ---------------- orchestration ----------------
extern "C" void kernel_launch(void* const* d_in, const int* in_sizes, int n_in,
                              void* d_out, int out_size)
{
    const float* V_a     = (const float*)d_in[0];
    const float* V_b     = (const float*)d_in[1];
    const float* D_a     = (const float*)d_in[2];
    const float* W_e     = (const float*)d_in[3];
    const float* gate_w  = (const float*)d_in[4];
    const float* conv1_w = (const float*)d_in[5];
    const float* conv2_w = (const float*)d_in[6];
    const float* bn1_g   = (const float*)d_in[7];
    const float* bn1_b   = (const float*)d_in[8];
    const float* bn2_g   = (const float*)d_in[9];
    const float* bn2_b   = (const float*)d_in[10];
    const float* cls1_w  = (const float*)d_in[11];
    const float* cls1_b  = (const float*)d_in[12];
    const float* cls2_w  = (const float*)d_in[13];
    const float* cls2_b  = (const float*)d_in[14];
    float* out = (float*)d_out;

    float *Wv, *S, *P, *att1, *att2, *x1, *x2, *y1, *y2;
    float *bnsc1, *bnsh1, *bnsc2, *bnsh2;
    cudaGetSymbolAddress((void**)&Wv,    g_Wv);
    cudaGetSymbolAddress((void**)&S,     g_S);
    cudaGetSymbolAddress((void**)&P,     g_P);
    cudaGetSymbolAddress((void**)&att1,  g_att1);
    cudaGetSymbolAddress((void**)&att2,  g_att2);
    cudaGetSymbolAddress((void**)&x1,    g_x1);
    cudaGetSymbolAddress((void**)&x2,    g_x2);
    cudaGetSymbolAddress((void**)&y1,    g_y1);
    cudaGetSymbolAddress((void**)&y2,    g_y2);
    cudaGetSymbolAddress((void**)&bnsc1, g_bnsc1);
    cudaGetSymbolAddress((void**)&bnsh1, g_bnsh1);
    cudaGetSymbolAddress((void**)&bnsc2, g_bnsc2);
    cudaGetSymbolAddress((void**)&bnsh2, g_bnsh2);

    const size_t CN = (size_t)CC * NPix;
    const size_t NN = (size_t)NPix * NPix;
    dim3 gSmall(57, 2, 2);    // N-tiles=ceil(3600/64), M-tiles=ceil(256/128), batch
    dim3 gBig(57, 29, 2);     // M=3600 -> 29 tiles of 128

    // 1) Wv = W_e @ V_a
    gemm_tiled<0,0><<<gSmall, 256>>>(W_e, V_a, Wv, CC, NPix, CC, 0, CN, CN);
    // 2) S = Wv^T @ V_b
    gemm_tiled<1,0><<<gBig, 256>>>(Wv, V_b, S, NPix, NPix, CC, CN, CN, NN);
    // 3) softmax stats
    rowstats_kernel<<<BB * NPix, 256>>>();
    colstats_part<<<dim3(15, NCHUNK, BB), 256>>>();
    colstats_comb<<<dim3(15, 1, BB), 256>>>();
    // 4) column-softmax probs -> Z_b = V_a @ Pcol -> gate
    expcol_kernel<<<BB * NPix, 256>>>();
    gemm_tiled<0,0><<<gSmall, 256>>>(V_a, P, att2, CC, NPix, NPix, CN, NN, CN);
    gate_kernel<<<dim3(15, 1, BB), 256>>>(att2, gate_w);
    // 5) row-softmax probs -> Z_a = V_b @ Prow^T -> gate
    exprow_kernel<<<BB * NPix, 256>>>();
    gemm_tiled<0,1><<<gSmall, 256>>>(V_b, P, att1, CC, NPix, NPix, CN, NN, CN);
    gate_kernel<<<dim3(15, 1, BB), 256>>>(att1, gate_w);
    // 6) convs (implicit GEMM over concat channels)
    conv3x3_gemm<<<gSmall, 256>>>(conv1_w, att1, V_a, D_a, x1, 3 * CC);
    conv3x3_gemm<<<gSmall, 256>>>(conv2_w, att2, V_b, V_b, x2, 2 * CC);
    // 7) BN stats + fused BN/ReLU/cls
    bnstats_kernel<<<CC, 256>>>(x1, bn1_g, bn1_b, bnsc1, bnsh1);
    bnstats_kernel<<<CC, 256>>>(x2, bn2_g, bn2_b, bnsc2, bnsh2);
    bncls_kernel<<<dim3(15, 1, BB), 256>>>(x1, bnsc1, bnsh1, cls1_w, cls1_b, y1);
    bncls_kernel<<<dim3(15, 1, BB), 256>>>(x2, bnsc2, bnsh2, cls2_w, cls2_b, y2);
    // 8) bilinear upsample + sigmoid -> d_out (x1 block then x2 block)
    const size_t total = 2ull * BB * NCls * HOUT * WOUT;
    int blocks = (int)((total + 255) / 256);
    resize_kernel<<<blocks, 256>>>(out);
}

// round 3
// speedup vs baseline: 1.5916x; 1.5916x over previous
#include <cuda_runtime.h>
#include <cstdint>
#include <math.h>

#define BB    2
#define CC    256
#define NPix  3600
#define NCls  2
#define HOUT  473
#define WOUT  473
#define NCHUNK 30

// ---------------- scratch ----------------
__device__ float g_E [BB*NPix*NPix];        // exp(S)
__device__ float g_Wv[BB*CC*NPix];
__device__ float g_rowinv[BB*NPix];
__device__ float g_colps[NCHUNK*BB*NPix];
__device__ float g_colinv[BB*NPix];
__device__ float g_att1[BB*CC*NPix];
__device__ float g_att2[BB*CC*NPix];
__device__ float g_x1[BB*CC*NPix];
__device__ float g_x2[BB*CC*NPix];
__device__ float g_bnsc1[CC], g_bnsh1[CC];
__device__ float g_bnsc2[CC], g_bnsh2[CC];
__device__ float g_y1[BB*NCls*NPix];
__device__ float g_y2[BB*NCls*NPix];

// ---------------- tf32 helpers ----------------
__device__ __forceinline__ uint32_t f2tf32(float v) {
    uint32_t r; asm("cvt.rna.tf32.f32 %0, %1;" : "=r"(r) : "f"(v)); return r;
}

// SMEM fragment layout (floats):
// A: [stage 2][s 4][mt 8][lane 32][reg 4] = 8192 floats
// B: 8192 + [stage 2][s 4][nt 16][lane 32][reg 2] = 8192 floats
#define A_IDX(st,s,mt,lane,r)  (((((st)*4+(s))*8+(mt))*128) + (lane)*4 + (r))
#define B_IDX(st,s,nt,lane,r)  (8192 + ((((st)*4+(s))*16+(nt))*64) + (lane)*2 + (r))
#define GEMM_SMEM (16384*4)

// mma.sync m16n8k8 tf32: A row-major fragment, B col-major fragment
#define MMA_TF32(accp, af, bf) \
    asm volatile("mma.sync.aligned.m16n8k8.row.col.f32.tf32.tf32.f32 " \
        "{%0,%1,%2,%3},{%4,%5,%6,%7},{%8,%9},{%0,%1,%2,%3};" \
        : "+f"((accp)[0]), "+f"((accp)[1]), "+f"((accp)[2]), "+f"((accp)[3]) \
        : "r"((af)[0]), "r"((af)[1]), "r"((af)[2]), "r"((af)[3]), \
          "r"((bf)[0]), "r"((bf)[1]))

// =============== GEMM body: C[M,N] = A*B, tile 128x128, Kchunk 32 ===============
// ALOAD 0: A(i,k)=A[i*lda+k]   ALOAD 1: A(i,k)=A[k*lda+i]
// BLOAD 0: B(k,j)=Bp[k*ldb+j]  BLOAD 1: B(k,j)=Bp[j*ldb+k]  BLOAD 2: im2col(s0,s1,s2)
// EEXP: store exp(acc).  BSCALE: multiply B(k,j) by Sc[j].
template<int ALOAD, int BLOAD, int EEXP, int BSCALE>
__device__ __forceinline__ void mma_body(
    const float* __restrict__ Ap, const float* __restrict__ Bp,
    const float* __restrict__ s1, const float* __restrict__ s2,
    const float* __restrict__ Sc, float* __restrict__ Cp,
    int Md, int Nd, int Kd, int lda, int ldb, int ldc,
    int z, int m0, int n0, float* sm)
{
    const int tid = threadIdx.x;
    const int lane = tid & 31, wid = tid >> 5;
    const int wm = wid >> 2, wn = wid & 3;   // warp tile: 64 rows x 32 cols

    float acc[4][4][4];
#pragma unroll
    for (int a = 0; a < 4; a++)
#pragma unroll
        for (int b = 0; b < 4; b++)
#pragma unroll
            for (int c = 0; c < 4; c++) acc[a][b][c] = 0.f;

    const int NC = (Kd + 31) >> 5;

    auto load_chunk = [&](int c) {
        const int st = c & 1;
        const int k0 = c << 5;
        // ---------- A tile ----------
        if (ALOAD == 0) {
            int row = tid >> 1, kb = (tid & 1) << 4;
            int gi = m0 + row;
            int mt = row >> 4, mb = (row >> 3) & 1, l4 = (row & 7) << 2;
#pragma unroll
            for (int q = 0; q < 4; q++) {
                int k = kb + q * 4;
                float4 v = make_float4(0.f, 0.f, 0.f, 0.f);
                if (gi < Md && (k0 + k) < Kd)
                    v = *(const float4*)(Ap + (size_t)gi * lda + k0 + k);
#pragma unroll
                for (int u = 0; u < 4; u++) {
                    int kk = k + u;
                    int s = kk >> 3, k8 = kk & 7;
                    sm[A_IDX(st, s, mt, l4 | (k8 & 3), ((k8 >> 2) << 1) | mb)] =
                        __uint_as_float(f2tf32(((const float*)&v)[u]));
                }
            }
        } else {
            int kk = tid >> 3, ib = (tid & 7) << 4;
            int s = kk >> 3, k8 = kk & 7;
#pragma unroll
            for (int q = 0; q < 4; q++) {
                int i = ib + q * 4;
                int gi = m0 + i;
                float4 v = make_float4(0.f, 0.f, 0.f, 0.f);
                if ((k0 + kk) < Kd && gi < Md)
                    v = *(const float4*)(Ap + (size_t)(k0 + kk) * lda + gi);
#pragma unroll
                for (int u = 0; u < 4; u++) {
                    int m = i + u;
                    sm[A_IDX(st, s, m >> 4, ((m & 7) << 2) | (k8 & 3),
                             ((k8 >> 2) << 1) | ((m >> 3) & 1))] =
                        __uint_as_float(f2tf32(((const float*)&v)[u]));
                }
            }
        }
        // ---------- B tile ----------
        if (BLOAD == 0) {
            int kk = tid >> 3, jb = (tid & 7) << 4;
            int s = kk >> 3, k8 = kk & 7;
#pragma unroll
            for (int q = 0; q < 4; q++) {
                int j = jb + q * 4;
                int gj = n0 + j;
                float4 v = make_float4(0.f, 0.f, 0.f, 0.f);
                if ((k0 + kk) < Kd && gj < Nd)
                    v = *(const float4*)(Bp + (size_t)(k0 + kk) * ldb + gj);
                float4 scv = make_float4(1.f, 1.f, 1.f, 1.f);
                if (BSCALE && gj < Nd) scv = *(const float4*)(Sc + gj);
#pragma unroll
                for (int u = 0; u < 4; u++) {
                    int n = j + u;
                    float x = ((const float*)&v)[u];
                    if (BSCALE) x *= ((const float*)&scv)[u];
                    sm[B_IDX(st, s, n >> 3, ((n & 7) << 2) | (k8 & 3), k8 >> 2)] =
                        __uint_as_float(f2tf32(x));
                }
            }
        } else if (BLOAD == 1) {
            int j = tid >> 1, kb = (tid & 1) << 4;
            int gj = n0 + j;
            float scj = 1.f;
            if (BSCALE && gj < Nd) scj = Sc[gj];
            int nt = j >> 3, l4 = (j & 7) << 2;
#pragma unroll
            for (int q = 0; q < 4; q++) {
                int k = kb + q * 4;
                float4 v = make_float4(0.f, 0.f, 0.f, 0.f);
                if (gj < Nd && (k0 + k) < Kd)
                    v = *(const float4*)(Bp + (size_t)gj * ldb + k0 + k);
#pragma unroll
                for (int u = 0; u < 4; u++) {
                    int kk = k + u;
                    int s = kk >> 3, k8 = kk & 7;
                    float x = ((const float*)&v)[u];
                    if (BSCALE) x *= scj;
                    sm[B_IDX(st, s, nt, l4 | (k8 & 3), k8 >> 2)] =
                        __uint_as_float(f2tf32(x));
                }
            }
        } else {
            int j = tid >> 1, kb = (tid & 1) << 4;
            int gj = n0 + j;
            bool jok = gj < Nd;
            int h = gj / 60, w = gj - h * 60;
            int nt = j >> 3, l4 = (j & 7) << 2;
#pragma unroll
            for (int q = 0; q < 16; q++) {
                int kk = kb + q;
                int kg = k0 + kk;
                float x = 0.f;
                if (jok && kg < Kd) {
                    int ci = kg / 9;
                    int rr = kg - ci * 9;
                    int kh = rr / 3, kw = rr - kh * 3;
                    const float* sp = (ci < 256) ? Bp : ((ci < 512) ? s1 : s2);
                    int cl = ci & 255;
                    int ih = h + kh - 1, iw = w + kw - 1;
                    if ((unsigned)ih < 60u && (unsigned)iw < 60u)
                        x = sp[(size_t)(z * CC + cl) * NPix + ih * 60 + iw];
                }
                int s = kk >> 3, k8 = kk & 7;
                sm[B_IDX(st, s, nt, l4 | (k8 & 3), k8 >> 2)] =
                    __uint_as_float(f2tf32(x));
            }
        }
    };

    load_chunk(0);
    __syncthreads();
    for (int c = 0; c < NC; c++) {
        if (c + 1 < NC) load_chunk(c + 1);
        const int st = c & 1;
#pragma unroll
        for (int s = 0; s < 4; s++) {
            uint32_t af[4][4], bf[4][2];
#pragma unroll
            for (int mt = 0; mt < 4; mt++) {
                float4 v = *(const float4*)&sm[A_IDX(st, s, wm * 4 + mt, lane, 0)];
                af[mt][0] = __float_as_uint(v.x); af[mt][1] = __float_as_uint(v.y);
                af[mt][2] = __float_as_uint(v.z); af[mt][3] = __float_as_uint(v.w);
            }
#pragma unroll
            for (int nt = 0; nt < 4; nt++) {
                float2 v = *(const float2*)&sm[B_IDX(st, s, wn * 4 + nt, lane, 0)];
                bf[nt][0] = __float_as_uint(v.x); bf[nt][1] = __float_as_uint(v.y);
            }
#pragma unroll
            for (int mt = 0; mt < 4; mt++)
#pragma unroll
                for (int nt = 0; nt < 4; nt++)
                    MMA_TF32(acc[mt][nt], af[mt], bf[nt]);
        }
        __syncthreads();
    }

    // epilogue: direct float2 stores
#pragma unroll
    for (int mt = 0; mt < 4; mt++) {
        int r0 = m0 + wm * 64 + mt * 16 + (lane >> 2);
#pragma unroll
        for (int nt = 0; nt < 4; nt++) {
            int c0 = n0 + wn * 32 + nt * 8 + (lane & 3) * 2;
            if (c0 < Nd) {
                if (r0 < Md) {
                    float2 v = make_float2(acc[mt][nt][0], acc[mt][nt][1]);
                    if (EEXP) { v.x = __expf(v.x); v.y = __expf(v.y); }
                    *(float2*)&Cp[(size_t)r0 * ldc + c0] = v;
                }
                if (r0 + 8 < Md) {
                    float2 v = make_float2(acc[mt][nt][2], acc[mt][nt][3]);
                    if (EEXP) { v.x = __expf(v.x); v.y = __expf(v.y); }
                    *(float2*)&Cp[(size_t)(r0 + 8) * ldc + c0] = v;
                }
            }
        }
    }
}

template<int ALOAD, int BLOAD, int EEXP, int BSCALE>
__global__ void __launch_bounds__(256)
mma_gemm(const float* __restrict__ A, const float* __restrict__ B0,
         const float* __restrict__ Bsc, float* __restrict__ Cc,
         int Md, int Nd, int Kd, int lda, int ldb, int ldc,
         size_t sA, size_t sB, size_t sC, size_t sScale)
{
    extern __shared__ float sm[];
    int z = blockIdx.z;
    mma_body<ALOAD, BLOAD, EEXP, BSCALE>(
        A + (size_t)z * sA, B0 + (size_t)z * sB, nullptr, nullptr,
        BSCALE ? (Bsc + (size_t)z * sScale) : nullptr,
        Cc + (size_t)z * sC,
        Md, Nd, Kd, lda, ldb, ldc, z, blockIdx.y * 128, blockIdx.x * 128, sm);
}

// combined conv1+conv2 (blockIdx.z: 0,1 -> conv1 b=0,1 ; 2,3 -> conv2 b=0,1)
__global__ void __launch_bounds__(256)
conv_gemm(const float* __restrict__ W1, const float* __restrict__ W2,
          const float* __restrict__ att1, const float* __restrict__ va,
          const float* __restrict__ da,
          const float* __restrict__ att2, const float* __restrict__ vb,
          float* __restrict__ x1, float* __restrict__ x2)
{
    extern __shared__ float sm[];
    int zz = blockIdx.z, br = zz >> 1, b = zz & 1;
    const float* Wt = br ? W2 : W1;
    int Kd = br ? (2 * CC * 9) : (3 * CC * 9);
    const float* s0 = br ? att2 : att1;
    const float* s1 = br ? vb : va;
    const float* s2 = br ? vb : da;
    float* out = (br ? x2 : x1) + (size_t)b * CC * NPix;
    mma_body<0, 2, 0, 0>(Wt, s0, s1, s2, nullptr, out,
        CC, NPix, Kd, Kd, 0, NPix, b, blockIdx.y * 128, blockIdx.x * 128, sm);
}

// ---------------- sums of E ----------------
__global__ void rowsum_kernel()
{
    int row = blockIdx.x;
    const float* Er = g_E + (size_t)row * NPix;
    float s = 0.f;
    for (int j = threadIdx.x; j < NPix; j += 256) s += Er[j];
    __shared__ float ss[256];
    ss[threadIdx.x] = s;
    __syncthreads();
    for (int off = 128; off; off >>= 1) {
        if (threadIdx.x < off) ss[threadIdx.x] += ss[threadIdx.x + off];
        __syncthreads();
    }
    if (threadIdx.x == 0) g_rowinv[row] = 1.f / ss[0];
}

__global__ void colsum_part()
{
    int m = blockIdx.x * 256 + threadIdx.x;
    int ch = blockIdx.y, b = blockIdx.z;
    if (m >= NPix) return;
    const int rows = NPix / NCHUNK;     // 120
    const float* Ep = g_E + (size_t)b * NPix * NPix + (size_t)(ch * rows) * NPix + m;
    float s0 = 0.f, s1 = 0.f, s2 = 0.f, s3 = 0.f;
    for (int n = 0; n < rows; n += 4) {
        s0 += Ep[(size_t)(n + 0) * NPix];
        s1 += Ep[(size_t)(n + 1) * NPix];
        s2 += Ep[(size_t)(n + 2) * NPix];
        s3 += Ep[(size_t)(n + 3) * NPix];
    }
    g_colps[(size_t)(ch * BB + b) * NPix + m] = (s0 + s1) + (s2 + s3);
}

__global__ void colsum_comb()
{
    int m = blockIdx.x * 256 + threadIdx.x;
    int b = blockIdx.z;
    if (m >= NPix) return;
    float s = 0.f;
#pragma unroll
    for (int ch = 0; ch < NCHUNK; ch++)
        s += g_colps[(size_t)(ch * BB + b) * NPix + m];
    g_colinv[b * NPix + m] = 1.f / s;
}

// ---------------- gate ----------------
__global__ void gate_kernel(float* __restrict__ Z, const float* __restrict__ gw)
{
    int b = blockIdx.z;
    int pix = blockIdx.x * 256 + threadIdx.x;
    __shared__ float w[CC];
    for (int c = threadIdx.x; c < CC; c += 256) w[c] = gw[c];
    __syncthreads();
    if (pix >= NPix) return;
    float* zp = Z + (size_t)b * CC * NPix + pix;
    float g = 0.f;
    for (int c = 0; c < CC; c++) g += w[c] * zp[(size_t)c * NPix];
    float sg = 1.f / (1.f + __expf(-g));
    for (int c = 0; c < CC; c++) zp[(size_t)c * NPix] *= sg;
}

// ---------------- BN stats ----------------
__global__ void bnstats_kernel(const float* __restrict__ x,
                               const float* __restrict__ gam,
                               const float* __restrict__ bet,
                               float* __restrict__ scale, float* __restrict__ shift)
{
    int c = blockIdx.x;
    float s = 0.f, q = 0.f;
    for (int b = 0; b < BB; b++) {
        const float* xp = x + (size_t)(b * CC + c) * NPix;
        for (int i = threadIdx.x; i < NPix; i += 256) {
            float v = xp[i];
            s += v; q += v * v;
        }
    }
    __shared__ float rs[256], rq[256];
    rs[threadIdx.x] = s; rq[threadIdx.x] = q;
    __syncthreads();
    for (int off = 128; off; off >>= 1) {
        if (threadIdx.x < off) {
            rs[threadIdx.x] += rs[threadIdx.x + off];
            rq[threadIdx.x] += rq[threadIdx.x + off];
        }
        __syncthreads();
    }
    if (threadIdx.x == 0) {
        const float inv = 1.f / (BB * NPix);
        float mean = rs[0] * inv;
        float var  = rq[0] * inv - mean * mean;
        float sc = gam[c] * rsqrtf(var + 1e-5f);
        scale[c] = sc;
        shift[c] = bet[c] - mean * sc;
    }
}

// ---------------- fused BN + ReLU + 1x1 cls ----------------
__global__ void bncls_kernel(const float* __restrict__ x,
                             const float* __restrict__ scale, const float* __restrict__ shift,
                             const float* __restrict__ cw, const float* __restrict__ cb,
                             float* __restrict__ y)
{
    int b = blockIdx.z;
    int pix = blockIdx.x * 256 + threadIdx.x;
    __shared__ float sc[CC], sh[CC], w0[CC], w1[CC];
    for (int c = threadIdx.x; c < CC; c += 256) {
        sc[c] = scale[c]; sh[c] = shift[c];
        w0[c] = cw[c];    w1[c] = cw[CC + c];
    }
    __syncthreads();
    if (pix >= NPix) return;
    const float* xp = x + (size_t)b * CC * NPix + pix;
    float a0 = cb[0], a1 = cb[1];
    for (int c = 0; c < CC; c++) {
        float v = xp[(size_t)c * NPix] * sc[c] + sh[c];
        v = fmaxf(v, 0.f);
        a0 += v * w0[c];
        a1 += v * w1[c];
    }
    y[(size_t)(b * NCls + 0) * NPix + pix] = a0;
    y[(size_t)(b * NCls + 1) * NPix + pix] = a1;
}

// ---------------- bilinear resize + sigmoid ----------------
__global__ void resize_kernel(float* __restrict__ out)
{
    const size_t per = (size_t)BB * NCls * HOUT * WOUT;
    size_t idx = (size_t)blockIdx.x * 256 + threadIdx.x;
    if (idx >= 2 * per) return;
    int t = idx >= per;
    size_t r = idx - (size_t)t * per;
    int x = (int)(r % WOUT); r /= WOUT;
    int y = (int)(r % HOUT); r /= HOUT;
    int kc = (int)(r % NCls);
    int b  = (int)(r / NCls);
    const float* src = (t ? g_y2 : g_y1) + (size_t)(b * NCls + kc) * NPix;

    const float sc = 60.f / 473.f;
    float syf = (y + 0.5f) * sc - 0.5f;
    float sxf = (x + 0.5f) * sc - 0.5f;
    float fy0 = floorf(syf), fx0 = floorf(sxf);
    float fy = syf - fy0,    fx = sxf - fx0;
    int y0 = (int)fy0, x0 = (int)fx0;
    int y1i = min(y0 + 1, 59), x1i = min(x0 + 1, 59);
    y0 = max(y0, 0); x0 = max(x0, 0);

    float v00 = src[y0  * 60 + x0 ];
    float v01 = src[y0  * 60 + x1i];
    float v10 = src[y1i * 60 + x0 ];
    float v11 = src[y1i * 60 + x1i];
    float vt = v00 + (v01 - v00) * fx;
    float vb = v10 + (v11 - v10) * fx;
    float v  = vt + (vb - vt) * fy;

    out[idx] = 1.f / (1.f + __expf(-v));
}

// ---------------- orchestration ----------------
extern "C" void kernel_launch(void* const* d_in, const int* in_sizes, int n_in,
                              void* d_out, int out_size)
{
    const float* V_a     = (const float*)d_in[0];
    const float* V_b     = (const float*)d_in[1];
    const float* D_a     = (const float*)d_in[2];
    const float* W_e     = (const float*)d_in[3];
    const float* gate_w  = (const float*)d_in[4];
    const float* conv1_w = (const float*)d_in[5];
    const float* conv2_w = (const float*)d_in[6];
    const float* bn1_g   = (const float*)d_in[7];
    const float* bn1_b   = (const float*)d_in[8];
    const float* bn2_g   = (const float*)d_in[9];
    const float* bn2_b   = (const float*)d_in[10];
    const float* cls1_w  = (const float*)d_in[11];
    const float* cls1_b  = (const float*)d_in[12];
    const float* cls2_w  = (const float*)d_in[13];
    const float* cls2_b  = (const float*)d_in[14];
    float* out = (float*)d_out;

    float *E, *Wv, *att1, *att2, *x1, *x2, *y1, *y2;
    float *rowinv, *colinv, *bnsc1, *bnsh1, *bnsc2, *bnsh2;
    cudaGetSymbolAddress((void**)&E,      g_E);
    cudaGetSymbolAddress((void**)&Wv,     g_Wv);
    cudaGetSymbolAddress((void**)&att1,   g_att1);
    cudaGetSymbolAddress((void**)&att2,   g_att2);
    cudaGetSymbolAddress((void**)&x1,     g_x1);
    cudaGetSymbolAddress((void**)&x2,     g_x2);
    cudaGetSymbolAddress((void**)&y1,     g_y1);
    cudaGetSymbolAddress((void**)&y2,     g_y2);
    cudaGetSymbolAddress((void**)&rowinv, g_rowinv);
    cudaGetSymbolAddress((void**)&colinv, g_colinv);
    cudaGetSymbolAddress((void**)&bnsc1,  g_bnsc1);
    cudaGetSymbolAddress((void**)&bnsh1,  g_bnsh1);
    cudaGetSymbolAddress((void**)&bnsc2,  g_bnsc2);
    cudaGetSymbolAddress((void**)&bnsh2,  g_bnsh2);

    cudaFuncSetAttribute(mma_gemm<0,0,0,0>, cudaFuncAttributeMaxDynamicSharedMemorySize, GEMM_SMEM);
    cudaFuncSetAttribute(mma_gemm<1,0,1,0>, cudaFuncAttributeMaxDynamicSharedMemorySize, GEMM_SMEM);
    cudaFuncSetAttribute(mma_gemm<0,0,0,1>, cudaFuncAttributeMaxDynamicSharedMemorySize, GEMM_SMEM);
    cudaFuncSetAttribute(mma_gemm<0,1,0,1>, cudaFuncAttributeMaxDynamicSharedMemorySize, GEMM_SMEM);
    cudaFuncSetAttribute(conv_gemm,         cudaFuncAttributeMaxDynamicSharedMemorySize, GEMM_SMEM);

    const size_t CN = (size_t)CC * NPix;
    const size_t NN = (size_t)NPix * NPix;
    dim3 gSmall(29, 2, 2);
    dim3 gBig(29, 29, 2);
    dim3 gConv(29, 2, 4);

    // 1) Wv = W_e @ V_a
    mma_gemm<0,0,0,0><<<gSmall, 256, GEMM_SMEM>>>(W_e, V_a, nullptr, Wv,
        CC, NPix, CC, CC, NPix, NPix, 0, CN, CN, 0);
    // 2) E = exp(Wv^T @ V_b)   (exp fused into epilogue; no max-shift needed)
    mma_gemm<1,0,1,0><<<gBig, 256, GEMM_SMEM>>>(Wv, V_b, nullptr, E,
        NPix, NPix, CC, NPix, NPix, NPix, CN, CN, NN, 0);
    // 3) row/col sums of E
    rowsum_kernel<<<BB * NPix, 256>>>();
    colsum_part<<<dim3(15, NCHUNK, BB), 256>>>();
    colsum_comb<<<dim3(15, 1, BB), 256>>>();
    // 4) Z_b = V_a @ (E * colinv[j])  -> gate
    mma_gemm<0,0,0,1><<<gSmall, 256, GEMM_SMEM>>>(V_a, E, colinv, att2,
        CC, NPix, NPix, NPix, NPix, NPix, CN, NN, CN, NPix);
    gate_kernel<<<dim3(15, 1, BB), 256>>>(att2, gate_w);
    // 5) Z_a = V_b @ (E^T * rowinv[j]) -> gate
    mma_gemm<0,1,0,1><<<gSmall, 256, GEMM_SMEM>>>(V_b, E, rowinv, att1,
        CC, NPix, NPix, NPix, NPix, NPix, CN, NN, CN, NPix);
    gate_kernel<<<dim3(15, 1, BB), 256>>>(att1, gate_w);
    // 6) both convs in one launch
    conv_gemm<<<gConv, 256, GEMM_SMEM>>>(conv1_w, conv2_w,
        att1, V_a, D_a, att2, V_b, x1, x2);
    // 7) BN + cls
    bnstats_kernel<<<CC, 256>>>(x1, bn1_g, bn1_b, bnsc1, bnsh1);
    bnstats_kernel<<<CC, 256>>>(x2, bn2_g, bn2_b, bnsc2, bnsh2);
    bncls_kernel<<<dim3(15, 1, BB), 256>>>(x1, bnsc1, bnsh1, cls1_w, cls1_b, y1);
    bncls_kernel<<<dim3(15, 1, BB), 256>>>(x2, bnsc2, bnsh2, cls2_w, cls2_b, y2);
    // 8) resize + sigmoid
    const size_t total = 2ull * BB * NCls * HOUT * WOUT;
    resize_kernel<<<(int)((total + 255) / 256), 256>>>(out);
}